// round 5
// baseline (speedup 1.0000x reference)
#include <cuda_runtime.h>
#include <math.h>

#define NRAYS   131072
#define NPTS    64
#define NIMP    64
#define NEARF   0.1f
#define FARF    2.0f
#define STEPF   ((FARF - NEARF) / 63.0f)
#define BLK     128
#define NBLK    (NRAYS / BLK)          // 1024
#define LOG2E_F 1.4426950408889634f

// scratch (no allocation allowed)
__device__ float g_rd[NRAYS];
__device__ float g_bmin[NBLK];
__device__ float g_bmax[NBLK];

__global__ __launch_bounds__(BLK) void nerf_main(const float* __restrict__ TM,
                                                 const float* __restrict__ WQ,
                                                 float* __restrict__ out)
{
    __shared__ float s_fd[NIMP * BLK];   // fine depths [q][tid]
    __shared__ float s_red[8];

    const int tid = threadIdx.x;
    const int r   = blockIdx.x * BLK + tid;
    const int bb_ = r >> 16;            // batch
    const int n   = r & 0xFFFF;         // pixel index within batch
    const int pi  = n >> 8;
    const int pj  = n & 0xFF;

    // camera dir
    const float cx = (1.0f - (float)pj * (2.0f / 255.0f)) * (1.0f / 4.2f);
    const float cy = (1.0f - (float)pi * (2.0f / 255.0f)) * (1.0f / 4.2f);

    const float* M = TM + bb_ * 12;
    const float dx = __ldg(M + 0) * cx + __ldg(M + 1) * cy + __ldg(M + 2);
    const float ox = __ldg(M + 3);
    const float dy = __ldg(M + 4) * cx + __ldg(M + 5) * cy + __ldg(M + 6);
    const float oy = __ldg(M + 7);
    const float dz = __ldg(M + 8) * cx + __ldg(M + 9) * cy + __ldg(M + 10);
    const float oz = __ldg(M + 11);

    // feat_j(d) = a[j] + d*b[j];  e_j(d) = exp(-feat_j) = 2^(a2[j] + d*b2[j])
    float a2[4], b2[4], einv[4], e0i[4];
#pragma unroll
    for (int c = 0; c < 4; c++) {
        const float w0 = __ldg(WQ + 0 * 4 + c);
        const float w1 = __ldg(WQ + 1 * 4 + c);
        const float w2 = __ldg(WQ + 2 * 4 + c);
        const float w3 = __ldg(WQ + 3 * 4 + c);
        const float w4 = __ldg(WQ + 4 * 4 + c);
        const float w5 = __ldg(WQ + 5 * 4 + c);
        const float bj = dx * w0 + dy * w1 + dz * w2;
        const float aj = ox * w0 + oy * w1 + oz * w2 + dx * w3 + dy * w4 + dz * w5;
        b2[c]   = -bj * LOG2E_F;
        a2[c]   = -aj * LOG2E_F;
        einv[c] = exp2f(STEPF * b2[c]);                // per-lattice-step ratio of e
        e0i[c]  = exp2f(fmaf(NEARF, b2[c], a2[c]));    // e at d = NEAR
    }

    // ---------------- Phase A: coarse march (1 RCP per sigmoid via recurrence) ----------------
    float ev0 = e0i[0], ev1 = e0i[1], ev2 = e0i[2], ev3 = e0i[3];
    float T = 1.0f, cv0 = 0.f, cv1 = 0.f, cv2 = 0.f, wsum = 0.f;
#pragma unroll 8
    for (int p = 0; p < NPTS; p++) {
        const float op = __fdividef(1.0f, 1.0f + ev0);
        const float v0 = __fdividef(1.0f, 1.0f + ev1);
        const float v1 = __fdividef(1.0f, 1.0f + ev2);
        const float v2 = __fdividef(1.0f, 1.0f + ev3);
        const float w = op * T;
        T = fmaf(-op, T, T);
        cv0 = fmaf(w, v0, cv0);
        cv1 = fmaf(w, v1, cv1);
        cv2 = fmaf(w, v2, cv2);
        wsum += w;
        ev0 *= einv[0]; ev1 *= einv[1]; ev2 *= einv[2]; ev3 *= einv[3];
    }
    {
        float* o = out + bb_ * 196608 + n;
        o[0]      = cv0;
        o[65536]  = cv1;
        o[131072] = cv2;
    }

    // ---------------- Phase B: inverse-CDF sampling (recurrence walker, no EX2) --------------
    {
        const float S    = wsum + (float)NPTS * 1e-5f;
        const float rcpS = __fdividef(1.0f, S);
        float evb = e0i[0];
        float Tb  = 1.0f;
        int   p   = 0;
        const float op0 = __fdividef(1.0f, 1.0f + evb);
        evb *= einv[0];
        Tb = fmaf(-op0, Tb, Tb);
        float cdf_prev = 0.0f;
        float cdf_cur  = (op0 + 1e-5f) * rcpS;
        float bin_prev = 0.0f;

        for (int ii = 0; ii <= NIMP; ii++) {
            const float u = (float)ii * (1.0f / (float)NIMP);
            while (p < NPTS - 1 && cdf_cur <= u) {
                p++;
                const float op = __fdividef(1.0f, 1.0f + evb);
                evb *= einv[0];
                const float w = op * Tb;
                Tb = fmaf(-op, Tb, Tb);
                cdf_prev = cdf_cur;
                cdf_cur += (w + 1e-5f) * rcpS;
            }
            float c0, c1, d0, d1;
            if (cdf_cur <= u) {                 // p == 63, idx = 64
                c0 = c1 = cdf_cur;
                d0 = d1 = fmaf((float)(NPTS - 1), STEPF, NEARF);
            } else if (p == 0) {                // idx = 0
                c0 = c1 = cdf_cur; d0 = d1 = NEARF;
            } else {                            // 1 <= idx <= 63
                c0 = cdf_prev; c1 = cdf_cur;
                d0 = fmaf((float)(p - 1), STEPF, NEARF);
                d1 = fmaf((float)p,       STEPF, NEARF);
            }
            float den = c1 - c0;
            den = (den < 1e-8f) ? 1.0f : den;
            const float tt  = __saturatef(__fdividef(u - c0, den));
            const float bin = fmaf(tt, d1 - d0, d0);
            if (ii > 0)
                s_fd[(ii - 1) * BLK + tid] = 0.5f * (bin_prev + bin);
            bin_prev = bin;
        }
    }

    // ---------------- Phase C: merged fine march (uniform 2-way merge, coarse wins ties) -----
    float T2 = 1.0f, fv0 = 0.f, fv1 = 0.f, fv2 = 0.f, ws2 = 0.f, rdacc = 0.f;
    {
        int cp = 0, fq = 0;
#pragma unroll 4
        for (int s = 0; s < NPTS + NIMP; s++) {
            const float dc = (cp < NPTS) ? fmaf((float)cp, STEPF, NEARF) : 1e30f;
            const float df = (fq < NIMP) ? s_fd[fq * BLK + tid] : 1e30f;
            float d;
            if (dc <= df) { d = dc; cp++; }
            else          { d = df; fq++; }
            const float e0 = exp2f(fmaf(d, b2[0], a2[0]));
            const float e1 = exp2f(fmaf(d, b2[1], a2[1]));
            const float e2 = exp2f(fmaf(d, b2[2], a2[2]));
            const float e3 = exp2f(fmaf(d, b2[3], a2[3]));
            const float op = __fdividef(1.0f, 1.0f + e0);
            const float v0 = __fdividef(1.0f, 1.0f + e1);
            const float v1 = __fdividef(1.0f, 1.0f + e2);
            const float v2 = __fdividef(1.0f, 1.0f + e3);
            const float w  = op * T2;
            T2 = fmaf(-op, T2, T2);
            fv0 = fmaf(w, v0, fv0);
            fv1 = fmaf(w, v1, fv1);
            fv2 = fmaf(w, v2, fv2);
            ws2 += w;
            rdacc = fmaf(w, d, rdacc);
        }
    }

    // f_img
    {
        float* o = out + 393216 + bb_ * 196608 + n;
        o[0]      = fv0;
        o[65536]  = fv1;
        o[131072] = fv2;
    }

    // ray depth: rd = sum(w*d) + (1 - clip(sum w,0,1)) * max(d_all)  (max == 2.0 globally)
    const float f_op = fminf(fmaxf(ws2, 0.0f), 1.0f);
    const float rd   = rdacc + (1.0f - f_op) * 2.0f;
    g_rd[r] = rd;

    // block-level min/max -> per-block slots (no init kernel, no atomics)
    float mn = rd, mx = rd;
#pragma unroll
    for (int o = 16; o > 0; o >>= 1) {
        mn = fminf(mn, __shfl_xor_sync(0xFFFFFFFFu, mn, o));
        mx = fmaxf(mx, __shfl_xor_sync(0xFFFFFFFFu, mx, o));
    }
    const int wid = tid >> 5;
    if ((tid & 31) == 0) { s_red[wid] = mn; s_red[4 + wid] = mx; }
    __syncthreads();
    if (tid == 0) {
        g_bmin[blockIdx.x] = fminf(fminf(s_red[0], s_red[1]), fminf(s_red[2], s_red[3]));
        g_bmax[blockIdx.x] = fmaxf(fmaxf(s_red[4], s_red[5]), fmaxf(s_red[6], s_red[7]));
    }
}

__global__ __launch_bounds__(256) void norm_depth(float* __restrict__ out)
{
    __shared__ float smn[8], smx[8];
    const int tid = threadIdx.x;

    float mn = 1e30f, mx = -1e30f;
#pragma unroll
    for (int i = 0; i < NBLK / 256; i++) {
        mn = fminf(mn, g_bmin[i * 256 + tid]);
        mx = fmaxf(mx, g_bmax[i * 256 + tid]);
    }
#pragma unroll
    for (int o = 16; o > 0; o >>= 1) {
        mn = fminf(mn, __shfl_xor_sync(0xFFFFFFFFu, mn, o));
        mx = fmaxf(mx, __shfl_xor_sync(0xFFFFFFFFu, mx, o));
    }
    if ((tid & 31) == 0) { smn[tid >> 5] = mn; smx[tid >> 5] = mx; }
    __syncthreads();
    if (tid == 0) {
        float m0 = smn[0], m1 = smx[0];
#pragma unroll
        for (int i = 1; i < 8; i++) { m0 = fminf(m0, smn[i]); m1 = fmaxf(m1, smx[i]); }
        smn[0] = m0; smx[0] = m1;
    }
    __syncthreads();
    const float gmn = smn[0];
    const float scl = __fdividef(1.0f, smx[0] - gmn);

    const int idx0 = blockIdx.x * 512 + tid;
    out[786432 + idx0]       = (g_rd[idx0]       - gmn) * scl;
    out[786432 + idx0 + 256] = (g_rd[idx0 + 256] - gmn) * scl;
}

extern "C" void kernel_launch(void* const* d_in, const int* in_sizes, int n_in,
                              void* d_out, int out_size)
{
    const float* TM = (const float*)d_in[0];   // transform_matrix (2,3,4)
    const float* WQ = (const float*)d_in[1];   // W_query (6,4)
    float* out = (float*)d_out;

    nerf_main<<<NBLK, BLK>>>(TM, WQ, out);
    norm_depth<<<NRAYS / 512, 256>>>(out);
}

// round 6
// speedup vs baseline: 1.5630x; 1.5630x over previous
#include <cuda_runtime.h>
#include <math.h>

#define NRAYS   131072
#define NPTS    64
#define NIMP    64
#define NEARF   0.1f
#define FARF    2.0f
#define STEPF   ((FARF - NEARF) / 63.0f)
#define BLK     128
#define NBLK    (NRAYS / BLK)          // 1024
#define LOG2E_F 1.4426950408889634f

// scratch (no allocation allowed)
__device__ float g_rd[NRAYS];
__device__ float g_bmin[NBLK];
__device__ float g_bmax[NBLK];

__device__ __forceinline__ float tanh_fast(float x) {
    float y;
    asm("tanh.approx.f32 %0, %1;" : "=f"(y) : "f"(x));
    return y;
}

__device__ __forceinline__ float depth_at(int p) {
    return fmaf((float)p, STEPF, NEARF);
}

__global__ __launch_bounds__(BLK) void nerf_main(const float* __restrict__ TM,
                                                 const float* __restrict__ WQ,
                                                 float* __restrict__ out)
{
    __shared__ float s_fd[NIMP * BLK];   // fine depths [q][tid]
    __shared__ float s_red[8];

    const int tid = threadIdx.x;
    const int r   = blockIdx.x * BLK + tid;
    const int bb_ = r >> 16;            // batch
    const int n   = r & 0xFFFF;         // pixel index within batch
    const int pi  = n >> 8;
    const int pj  = n & 0xFF;

    // camera dir
    const float cx = (1.0f - (float)pj * (2.0f / 255.0f)) * (1.0f / 4.2f);
    const float cy = (1.0f - (float)pi * (2.0f / 255.0f)) * (1.0f / 4.2f);

    const float* M = TM + bb_ * 12;
    const float dx = __ldg(M + 0) * cx + __ldg(M + 1) * cy + __ldg(M + 2);
    const float ox = __ldg(M + 3);
    const float dy = __ldg(M + 4) * cx + __ldg(M + 5) * cy + __ldg(M + 6);
    const float oy = __ldg(M + 7);
    const float dz = __ldg(M + 8) * cx + __ldg(M + 9) * cy + __ldg(M + 10);
    const float oz = __ldg(M + 11);

    // feat_j(d) = a[j] + d*b[j]
    // opacity (j=0): e(d) = exp(-feat0) = 2^(a2o + d*b2o); op = 1/(1+e)   [exact path]
    // values (j=1..3): v = sigmoid(feat) = 0.5 + 0.5*tanh(0.5*feat)       [tanh.approx]
    float a2o, b2o, ah[3], bh[3];
#pragma unroll
    for (int c = 0; c < 4; c++) {
        const float w0 = __ldg(WQ + 0 * 4 + c);
        const float w1 = __ldg(WQ + 1 * 4 + c);
        const float w2 = __ldg(WQ + 2 * 4 + c);
        const float w3 = __ldg(WQ + 3 * 4 + c);
        const float w4 = __ldg(WQ + 4 * 4 + c);
        const float w5 = __ldg(WQ + 5 * 4 + c);
        const float bj = dx * w0 + dy * w1 + dz * w2;
        const float aj = ox * w0 + oy * w1 + oz * w2 + dx * w3 + dy * w4 + dz * w5;
        if (c == 0) {
            a2o = -aj * LOG2E_F;
            b2o = -bj * LOG2E_F;
        } else {
            ah[c - 1] = 0.5f * aj;
            bh[c - 1] = 0.5f * bj;
        }
    }

    // ---------------- Phase A: coarse march (independent per-sample sigmoids) ----------------
    float T = 1.0f, cv0 = 0.f, cv1 = 0.f, cv2 = 0.f, wsum = 0.f;
#pragma unroll 8
    for (int p = 0; p < NPTS; p++) {
        const float d  = depth_at(p);
        const float e0 = exp2f(fmaf(d, b2o, a2o));
        const float op = __fdividef(1.0f, 1.0f + e0);
        const float v0 = fmaf(tanh_fast(fmaf(d, bh[0], ah[0])), 0.5f, 0.5f);
        const float v1 = fmaf(tanh_fast(fmaf(d, bh[1], ah[1])), 0.5f, 0.5f);
        const float v2 = fmaf(tanh_fast(fmaf(d, bh[2], ah[2])), 0.5f, 0.5f);
        const float w = op * T;
        T = fmaf(-op, T, T);
        cv0 = fmaf(w, v0, cv0);
        cv1 = fmaf(w, v1, cv1);
        cv2 = fmaf(w, v2, cv2);
        wsum += w;
    }
    {
        float* o = out + bb_ * 196608 + n;
        o[0]      = cv0;
        o[65536]  = cv1;
        o[131072] = cv2;
    }

    // ---------------- Phase B: inverse-CDF sampling (merge scan, exact opacity) -------------
    {
        const float S    = wsum + (float)NPTS * 1e-5f;
        const float rcpS = __fdividef(1.0f, S);
        float Tb = 1.0f;
        int   p  = 0;
        const float ee0 = exp2f(fmaf(NEARF, b2o, a2o));
        const float op0 = __fdividef(1.0f, 1.0f + ee0);
        Tb = fmaf(-op0, Tb, Tb);
        float cdf_prev = 0.0f;
        float cdf_cur  = (op0 + 1e-5f) * rcpS;
        float bin_prev = 0.0f;

        for (int ii = 0; ii <= NIMP; ii++) {
            const float u = (float)ii * (1.0f / (float)NIMP);
            while (p < NPTS - 1 && cdf_cur <= u) {
                p++;
                const float d  = depth_at(p);
                const float e0 = exp2f(fmaf(d, b2o, a2o));
                const float op = __fdividef(1.0f, 1.0f + e0);
                const float w  = op * Tb;
                Tb = fmaf(-op, Tb, Tb);
                cdf_prev = cdf_cur;
                cdf_cur += (w + 1e-5f) * rcpS;
            }
            float c0, c1, d0, d1;
            if (cdf_cur <= u) {                 // p == 63, idx = 64
                c0 = c1 = cdf_cur;
                d0 = d1 = depth_at(NPTS - 1);
            } else if (p == 0) {                // idx = 0
                c0 = c1 = cdf_cur; d0 = d1 = NEARF;
            } else {                            // 1 <= idx <= 63
                c0 = cdf_prev; c1 = cdf_cur;
                d0 = depth_at(p - 1);
                d1 = depth_at(p);
            }
            float den = c1 - c0;
            den = (den < 1e-8f) ? 1.0f : den;
            const float tt  = __saturatef(__fdividef(u - c0, den));
            const float bin = fmaf(tt, d1 - d0, d0);
            if (ii > 0)
                s_fd[(ii - 1) * BLK + tid] = 0.5f * (bin_prev + bin);
            bin_prev = bin;
        }
    }

    // ---------------- Phase C: merged fine march (uniform 2-way merge, coarse wins ties) -----
    float T2 = 1.0f, fv0 = 0.f, fv1 = 0.f, fv2 = 0.f, ws2 = 0.f, rdacc = 0.f;
    {
        int cp = 0, fq = 0;
#pragma unroll 4
        for (int s = 0; s < NPTS + NIMP; s++) {
            const float dc = (cp < NPTS) ? depth_at(cp) : 1e30f;
            const float df = (fq < NIMP) ? s_fd[fq * BLK + tid] : 1e30f;
            float d;
            if (dc <= df) { d = dc; cp++; }
            else          { d = df; fq++; }
            const float e0 = exp2f(fmaf(d, b2o, a2o));
            const float op = __fdividef(1.0f, 1.0f + e0);
            const float v0 = fmaf(tanh_fast(fmaf(d, bh[0], ah[0])), 0.5f, 0.5f);
            const float v1 = fmaf(tanh_fast(fmaf(d, bh[1], ah[1])), 0.5f, 0.5f);
            const float v2 = fmaf(tanh_fast(fmaf(d, bh[2], ah[2])), 0.5f, 0.5f);
            const float w  = op * T2;
            T2 = fmaf(-op, T2, T2);
            fv0 = fmaf(w, v0, fv0);
            fv1 = fmaf(w, v1, fv1);
            fv2 = fmaf(w, v2, fv2);
            ws2 += w;
            rdacc = fmaf(w, d, rdacc);
        }
    }

    // f_img
    {
        float* o = out + 393216 + bb_ * 196608 + n;
        o[0]      = fv0;
        o[65536]  = fv1;
        o[131072] = fv2;
    }

    // ray depth: rd = sum(w*d) + (1 - clip(sum w,0,1)) * max(d_all)  (max == 2.0 globally)
    const float f_op = fminf(fmaxf(ws2, 0.0f), 1.0f);
    const float rd   = rdacc + (1.0f - f_op) * 2.0f;
    g_rd[r] = rd;

    // block-level min/max -> per-block slots (no init kernel, no atomics)
    float mn = rd, mx = rd;
#pragma unroll
    for (int o = 16; o > 0; o >>= 1) {
        mn = fminf(mn, __shfl_xor_sync(0xFFFFFFFFu, mn, o));
        mx = fmaxf(mx, __shfl_xor_sync(0xFFFFFFFFu, mx, o));
    }
    const int wid = tid >> 5;
    if ((tid & 31) == 0) { s_red[wid] = mn; s_red[4 + wid] = mx; }
    __syncthreads();
    if (tid == 0) {
        g_bmin[blockIdx.x] = fminf(fminf(s_red[0], s_red[1]), fminf(s_red[2], s_red[3]));
        g_bmax[blockIdx.x] = fmaxf(fmaxf(s_red[4], s_red[5]), fmaxf(s_red[6], s_red[7]));
    }
}

__global__ __launch_bounds__(256) void norm_depth(float* __restrict__ out)
{
    __shared__ float smn[8], smx[8];
    const int tid = threadIdx.x;

    float mn = 1e30f, mx = -1e30f;
#pragma unroll
    for (int i = 0; i < NBLK / 256; i++) {
        mn = fminf(mn, g_bmin[i * 256 + tid]);
        mx = fmaxf(mx, g_bmax[i * 256 + tid]);
    }
#pragma unroll
    for (int o = 16; o > 0; o >>= 1) {
        mn = fminf(mn, __shfl_xor_sync(0xFFFFFFFFu, mn, o));
        mx = fmaxf(mx, __shfl_xor_sync(0xFFFFFFFFu, mx, o));
    }
    if ((tid & 31) == 0) { smn[tid >> 5] = mn; smx[tid >> 5] = mx; }
    __syncthreads();
    if (tid == 0) {
        float m0 = smn[0], m1 = smx[0];
#pragma unroll
        for (int i = 1; i < 8; i++) { m0 = fminf(m0, smn[i]); m1 = fmaxf(m1, smx[i]); }
        smn[0] = m0; smx[0] = m1;
    }
    __syncthreads();
    const float gmn = smn[0];
    const float scl = __fdividef(1.0f, smx[0] - gmn);

    const int idx0 = blockIdx.x * 512 + tid;
    out[786432 + idx0]       = (g_rd[idx0]       - gmn) * scl;
    out[786432 + idx0 + 256] = (g_rd[idx0 + 256] - gmn) * scl;
}

extern "C" void kernel_launch(void* const* d_in, const int* in_sizes, int n_in,
                              void* d_out, int out_size)
{
    const float* TM = (const float*)d_in[0];   // transform_matrix (2,3,4)
    const float* WQ = (const float*)d_in[1];   // W_query (6,4)
    float* out = (float*)d_out;

    nerf_main<<<NBLK, BLK>>>(TM, WQ, out);
    norm_depth<<<NRAYS / 512, 256>>>(out);
}

// round 10
// speedup vs baseline: 2.0445x; 1.3081x over previous
#include <cuda_runtime.h>
#include <math.h>

#define NRAYS   131072
#define NPTS    64
#define NIMP    64
#define NEARF   0.1f
#define FARF    2.0f
#define STEPF   ((FARF - NEARF) / 63.0f)
#define BLK     128
#define NBLK    (NRAYS / BLK)          // 1024

// scratch (no allocation allowed)
__device__ float g_rd[NRAYS];
__device__ float g_bmin[NBLK];
__device__ float g_bmax[NBLK];

__device__ __forceinline__ float tanh_fast(float x) {
    float y;
    asm("tanh.approx.f32 %0, %1;" : "=f"(y) : "f"(x));
    return y;
}

__device__ __forceinline__ float depth_at(int p) {
    return fmaf((float)p, STEPF, NEARF);
}

__global__ __launch_bounds__(BLK) void nerf_main(const float* __restrict__ TM,
                                                 const float* __restrict__ WQ,
                                                 float* __restrict__ out)
{
    __shared__ float s_fd[NIMP * BLK];   // fine depths [q][tid]
    __shared__ float s_red[8];

    const int tid = threadIdx.x;
    const int r   = blockIdx.x * BLK + tid;
    const int bb_ = r >> 16;            // batch
    const int n   = r & 0xFFFF;         // pixel index within batch
    const int pi  = n >> 8;
    const int pj  = n & 0xFF;

    // camera dir
    const float cx = (1.0f - (float)pj * (2.0f / 255.0f)) * (1.0f / 4.2f);
    const float cy = (1.0f - (float)pi * (2.0f / 255.0f)) * (1.0f / 4.2f);

    const float* M = TM + bb_ * 12;
    const float dx = __ldg(M + 0) * cx + __ldg(M + 1) * cy + __ldg(M + 2);
    const float ox = __ldg(M + 3);
    const float dy = __ldg(M + 4) * cx + __ldg(M + 5) * cy + __ldg(M + 6);
    const float oy = __ldg(M + 7);
    const float dz = __ldg(M + 8) * cx + __ldg(M + 9) * cy + __ldg(M + 10);
    const float oz = __ldg(M + 11);

    // feat_j(d) = a[j] + d*b[j];  sigmoid(x) = 0.5 + 0.5*tanh(0.5*x)  (all 4 channels)
    float ah[4], bh[4];   // pre-halved: h_j(d) = ah[j] + d*bh[j], sig = fma(tanh(h),.5,.5)
#pragma unroll
    for (int c = 0; c < 4; c++) {
        const float w0 = __ldg(WQ + 0 * 4 + c);
        const float w1 = __ldg(WQ + 1 * 4 + c);
        const float w2 = __ldg(WQ + 2 * 4 + c);
        const float w3 = __ldg(WQ + 3 * 4 + c);
        const float w4 = __ldg(WQ + 4 * 4 + c);
        const float w5 = __ldg(WQ + 5 * 4 + c);
        const float bj = dx * w0 + dy * w1 + dz * w2;
        const float aj = ox * w0 + oy * w1 + oz * w2 + dx * w3 + dy * w4 + dz * w5;
        ah[c] = 0.5f * aj;
        bh[c] = 0.5f * bj;
    }

    // ---------------- Phase A: coarse march (independent per-sample sigmoids) ----------------
    float T = 1.0f, ct0 = 0.f, ct1 = 0.f, ct2 = 0.f, wsum = 0.f;
#pragma unroll 8
    for (int p = 0; p < NPTS; p++) {
        const float d  = depth_at(p);                 // constant-folded under unroll
        const float t0 = tanh_fast(fmaf(d, bh[0], ah[0]));
        const float t1 = tanh_fast(fmaf(d, bh[1], ah[1]));
        const float t2 = tanh_fast(fmaf(d, bh[2], ah[2]));
        const float t3 = tanh_fast(fmaf(d, bh[3], ah[3]));
        const float op = fmaf(t0, 0.5f, 0.5f);
        const float w  = op * T;
        T = fmaf(-op, T, T);
        ct0 = fmaf(w, t1, ct0);                       // accumulate w*t; fold 0.5s at end
        ct1 = fmaf(w, t2, ct1);
        ct2 = fmaf(w, t3, ct2);
        wsum += w;
    }
    {
        float* o = out + bb_ * 196608 + n;
        o[0]      = 0.5f * (wsum + ct0);
        o[65536]  = 0.5f * (wsum + ct1);
        o[131072] = 0.5f * (wsum + ct2);
    }

    // ---------------- Phase B: inverse-CDF sampling (merge scan) -----------------------------
    {
        const float S    = wsum + (float)NPTS * 1e-5f;
        const float rcpS = __fdividef(1.0f, S);
        float Tb = 1.0f;
        int   p  = 0;
        float dp = NEARF;                             // depth at current p
        const float op0 = fmaf(tanh_fast(fmaf(NEARF, bh[0], ah[0])), 0.5f, 0.5f);
        Tb = fmaf(-op0, Tb, Tb);
        float cdf_prev = 0.0f;
        float cdf_cur  = (op0 + 1e-5f) * rcpS;
        float bin_prev = 0.0f;

        for (int ii = 0; ii <= NIMP; ii++) {
            const float u = (float)ii * (1.0f / (float)NIMP);
            while (p < NPTS - 1 && cdf_cur <= u) {
                p++;
                dp += STEPF;
                const float op = fmaf(tanh_fast(fmaf(dp, bh[0], ah[0])), 0.5f, 0.5f);
                const float w  = op * Tb;
                Tb = fmaf(-op, Tb, Tb);
                cdf_prev = cdf_cur;
                cdf_cur += (w + 1e-5f) * rcpS;
            }
            float c0, c1, d0, d1;
            if (cdf_cur <= u) {                 // p == 63, idx = 64
                c0 = c1 = cdf_cur;
                d0 = d1 = dp;
            } else if (p == 0) {                // idx = 0
                c0 = c1 = cdf_cur; d0 = d1 = NEARF;
            } else {                            // 1 <= idx <= 63
                c0 = cdf_prev; c1 = cdf_cur;
                d0 = dp - STEPF;
                d1 = dp;
            }
            float den = c1 - c0;
            den = (den < 1e-8f) ? 1.0f : den;
            const float tt  = __saturatef(__fdividef(u - c0, den));
            const float bin = fmaf(tt, d1 - d0, d0);
            if (ii > 0)
                s_fd[(ii - 1) * BLK + tid] = 0.5f * (bin_prev + bin);
            bin_prev = bin;
        }
    }

    // ---------------- Phase C: merged fine march (uniform 2-way merge, coarse wins ties) -----
    float T2 = 1.0f, ft0 = 0.f, ft1 = 0.f, ft2 = 0.f, ws2 = 0.f, rdacc = 0.f;
    {
        float cpf = 0.0f;                             // exact integer-valued float counter
        int fq = 0;
#pragma unroll 4
        for (int s = 0; s < NPTS + NIMP; s++) {
            const float dc = fmaf(cpf, STEPF, NEARF); // == depth_at(cp), exact; >2.0 when done
            const float df = (fq < NIMP) ? s_fd[fq * BLK + tid] : 1e30f;
            float d;
            if (dc <= df) { d = dc; cpf += 1.0f; }
            else          { d = df; fq++; }
            const float t0 = tanh_fast(fmaf(d, bh[0], ah[0]));
            const float t1 = tanh_fast(fmaf(d, bh[1], ah[1]));
            const float t2 = tanh_fast(fmaf(d, bh[2], ah[2]));
            const float t3 = tanh_fast(fmaf(d, bh[3], ah[3]));
            const float op = fmaf(t0, 0.5f, 0.5f);
            const float w  = op * T2;
            T2 = fmaf(-op, T2, T2);
            ft0 = fmaf(w, t1, ft0);
            ft1 = fmaf(w, t2, ft1);
            ft2 = fmaf(w, t3, ft2);
            ws2 += w;
            rdacc = fmaf(w, d, rdacc);
        }
    }

    // f_img
    {
        float* o = out + 393216 + bb_ * 196608 + n;
        o[0]      = 0.5f * (ws2 + ft0);
        o[65536]  = 0.5f * (ws2 + ft1);
        o[131072] = 0.5f * (ws2 + ft2);
    }

    // ray depth: rd = sum(w*d) + (1 - clip(sum w,0,1)) * max(d_all)  (max == 2.0 globally)
    const float f_op = fminf(fmaxf(ws2, 0.0f), 1.0f);
    const float rd   = rdacc + (1.0f - f_op) * 2.0f;
    g_rd[r] = rd;

    // block-level min/max -> per-block slots (no init kernel, no atomics)
    float mn = rd, mx = rd;
#pragma unroll
    for (int o = 16; o > 0; o >>= 1) {
        mn = fminf(mn, __shfl_xor_sync(0xFFFFFFFFu, mn, o));
        mx = fmaxf(mx, __shfl_xor_sync(0xFFFFFFFFu, mx, o));
    }
    const int wid = tid >> 5;
    if ((tid & 31) == 0) { s_red[wid] = mn; s_red[4 + wid] = mx; }
    __syncthreads();
    if (tid == 0) {
        g_bmin[blockIdx.x] = fminf(fminf(s_red[0], s_red[1]), fminf(s_red[2], s_red[3]));
        g_bmax[blockIdx.x] = fmaxf(fmaxf(s_red[4], s_red[5]), fmaxf(s_red[6], s_red[7]));
    }
}

__global__ __launch_bounds__(256) void norm_depth(float* __restrict__ out)
{
    __shared__ float smn[8], smx[8];
    const int tid = threadIdx.x;

    float mn = 1e30f, mx = -1e30f;
#pragma unroll
    for (int i = 0; i < NBLK / 256; i++) {
        mn = fminf(mn, g_bmin[i * 256 + tid]);
        mx = fmaxf(mx, g_bmax[i * 256 + tid]);
    }
#pragma unroll
    for (int o = 16; o > 0; o >>= 1) {
        mn = fminf(mn, __shfl_xor_sync(0xFFFFFFFFu, mn, o));
        mx = fmaxf(mx, __shfl_xor_sync(0xFFFFFFFFu, mx, o));
    }
    if ((tid & 31) == 0) { smn[tid >> 5] = mn; smx[tid >> 5] = mx; }
    __syncthreads();
    if (tid == 0) {
        float m0 = smn[0], m1 = smx[0];
#pragma unroll
        for (int i = 1; i < 8; i++) { m0 = fminf(m0, smn[i]); m1 = fmaxf(m1, smx[i]); }
        smn[0] = m0; smx[0] = m1;
    }
    __syncthreads();
    const float gmn = smn[0];
    const float scl = __fdividef(1.0f, smx[0] - gmn);

    const int idx0 = blockIdx.x * 512 + tid;
    out[786432 + idx0]       = (g_rd[idx0]       - gmn) * scl;
    out[786432 + idx0 + 256] = (g_rd[idx0 + 256] - gmn) * scl;
}

extern "C" void kernel_launch(void* const* d_in, const int* in_sizes, int n_in,
                              void* d_out, int out_size)
{
    const float* TM = (const float*)d_in[0];   // transform_matrix (2,3,4)
    const float* WQ = (const float*)d_in[1];   // W_query (6,4)
    float* out = (float*)d_out;

    nerf_main<<<NBLK, BLK>>>(TM, WQ, out);
    norm_depth<<<NRAYS / 512, 256>>>(out);
}